// round 5
// baseline (speedup 1.0000x reference)
#include <cuda_runtime.h>

#define NTOK 65536
#define EDIM 256
#define NE   1024

#define OFF_ZQ   0
#define OFF_LOSS 16777216
#define OFF_IDX  16777217
#define OFF_SAMP 16842753
#define OFF_MCD  16844801
#define OFF_MCV  16844802

typedef unsigned long long ull;

static __device__ float  g_zz[NTOK];
static __device__ float  g_ee[NE];
static __device__ int    g_idx[NTOK];
static __device__ float  g_cd[NE * NE];
static __device__ double g_loss_acc;
static __device__ double g_min2_acc;
static __device__ double g_var_acc;

// Packed dual-fp32 FMA (Blackwell; PTX-only)
__device__ __forceinline__ ull ffma2(ull a, ull b, ull c) {
    ull d;
    asm("fma.rn.f32x2 %0, %1, %2, %3;" : "=l"(d) : "l"(a), "l"(b), "l"(c));
    return d;
}
__device__ __forceinline__ ull swap64(ull a) {
    return (a >> 32) | (a << 32);
}

__device__ __forceinline__ void cp_async16(void* sdst, const void* gsrc) {
    unsigned sa = (unsigned)__cvta_generic_to_shared(sdst);
    asm volatile("cp.async.ca.shared.global [%0], [%1], 16;\n" ::
                 "r"(sa), "l"(gsrc));
}
__device__ __forceinline__ void cp_commit() {
    asm volatile("cp.async.commit_group;\n");
}
__device__ __forceinline__ void cp_wait0() {
    asm volatile("cp.async.wait_group 0;\n" ::: "memory");
}

// ---------------------------------------------------------------------------
__global__ void init_kernel(float* __restrict__ out) {
    int i = blockIdx.x * blockDim.x + threadIdx.x;
    if (i < 2048) out[OFF_SAMP + i] = 0.0f;
    if (i == 0) { g_loss_acc = 0.0; g_min2_acc = 0.0; g_var_acc = 0.0; }
}

__global__ void ee_kernel(const float* __restrict__ emb) {
    int n = blockIdx.x * blockDim.x + threadIdx.x;
    if (n >= NE) return;
    const float* r = emb + (size_t)n * EDIM;
    float acc = 0.0f;
    for (int c = 0; c < EDIM; c++) { float v = r[c]; acc = fmaf(v, v, acc); }
    g_ee[n] = acc;
}

__global__ void zz_kernel(const float* __restrict__ z) {
    int t = blockIdx.x * blockDim.x + threadIdx.x;
    int b = t >> 15, s = t & 32767;
    const float* base = z + ((size_t)b << 23) + s;
    float acc = 0.0f;
#pragma unroll 8
    for (int c = 0; c < EDIM; c++) {
        float v = base[(size_t)c << 15];
        acc = fmaf(v, v, acc);
    }
    g_zz[t] = acc;
}

// ---------------------------------------------------------------------------
// Distance GEMM + argmin. Block tile: 128 tokens x 128 codes (8 nt tiles).
// 256 threads: tx=tid&7 owns 16 contiguous codes (tx*16..+15), ty=tid>>3 owns
// 4 contiguous tokens (ty*4..+3). Natural-pair FFMA2: lanes carry
// (tokEven*codeEven, tokOdd*codeOdd) from adjacent register pairs; the
// off-diagonal combos use a half-swapped A pair (4 MOVs/kk). No smem
// duplication: As/Bs are plain float[16][128], B read via LDS.128 (1 wf each).
// Numerics bit-identical to R2-R4 (per-(t,j) sequential k, same epilogue).
__global__ void __launch_bounds__(256, 2)
dist_kernel(const float* __restrict__ z, const float* __restrict__ emb,
            float* __restrict__ out) {
    extern __shared__ char smem_raw[];
    // [0    , 16384): As[2][16][128] float  (A: z tile, k-major)
    // [16384, 32768): Bs[2][16][128] float  (B: emb tile, [k][code])
    float (*As)[16][128] = (float(*)[16][128])smem_raw;
    float (*Bs)[16][128] = (float(*)[16][128])(smem_raw + 16384);

    int tid = threadIdx.x;
    int tx = tid & 7;        // code group
    int ty = tid >> 3;       // token group
    int t0 = blockIdx.x * 128;
    int b = t0 >> 15, s0 = t0 & 32767;
    const float* zb = z + ((size_t)b << 23) + s0;
    // B staging: thread stages 8 floats of one emb row
    int brow  = tid & 127;
    int bhalf = tid >> 7;

    float tzz[4];
#pragma unroll
    for (int i = 0; i < 4; i++) tzz[i] = g_zz[t0 + ty * 4 + i];

    float best[4];
    int   bidx[4];
#pragma unroll
    for (int i = 0; i < 4; i++) { best[i] = 3.4e38f; bidx[i] = 0; }

    for (int nt = 0; nt < 8; nt++) {
        int n0 = nt * 128;
        const float* bsrc = emb + (size_t)(n0 + brow) * EDIM + bhalf * 8;

        ull accA[2][8], accB[2][8];
#pragma unroll
        for (int p = 0; p < 2; p++)
#pragma unroll
            for (int j = 0; j < 8; j++) { accA[p][j] = 0ull; accB[p][j] = 0ull; }

        float bq[8];

        // ---- prologue: stage kc=0 into buffer 0 ----
        {
            float4 v0 = *(const float4*)(bsrc);
            float4 v1 = *(const float4*)(bsrc + 4);
            bq[0]=v0.x; bq[1]=v0.y; bq[2]=v0.z; bq[3]=v0.w;
            bq[4]=v1.x; bq[5]=v1.y; bq[6]=v1.z; bq[7]=v1.w;
#pragma unroll
            for (int c = 0; c < 2; c++) {
                int lin = c * 256 + tid;
                int row = lin >> 5, col = (lin & 31) * 4;
                cp_async16(&As[0][row][col], zb + ((size_t)row << 15) + col);
            }
            cp_commit();
#pragma unroll
            for (int q = 0; q < 8; q++)
                Bs[0][bhalf * 8 + q][brow] = bq[q];
            cp_wait0();
        }
        __syncthreads();

        for (int kc = 0; kc < 16; kc++) {
            int buf = kc & 1;
            // ---- issue staging for kc+1 (latency hidden under compute) ----
            if (kc < 15) {
                const float* p1 = bsrc + (kc + 1) * 16;
                float4 v0 = *(const float4*)(p1);
                float4 v1 = *(const float4*)(p1 + 4);
                bq[0]=v0.x; bq[1]=v0.y; bq[2]=v0.z; bq[3]=v0.w;
                bq[4]=v1.x; bq[5]=v1.y; bq[6]=v1.z; bq[7]=v1.w;
#pragma unroll
                for (int c = 0; c < 2; c++) {
                    int lin = c * 256 + tid;
                    int row = lin >> 5, col = (lin & 31) * 4;
                    cp_async16(&As[buf ^ 1][row][col],
                               zb + ((size_t)((kc + 1) * 16 + row) << 15) + col);
                }
                cp_commit();
            }
            // ---- compute kc from buf ----
#pragma unroll
            for (int kk = 0; kk < 16; kk++) {
                // A: 4 tokens as 2 natural ull pairs + 2 half-swaps
                ulonglong2 av = *(const ulonglong2*)&As[buf][kk][ty * 4];
                ull a01 = av.x, a23 = av.y;
                ull s01 = swap64(a01), s23 = swap64(a23);
                // B: 16 codes as 4 LDS.128 (8 natural ull pairs)
#pragma unroll
                for (int q = 0; q < 4; q++) {
                    ulonglong2 bb =
                        *(const ulonglong2*)&Bs[buf][kk][tx * 16 + q * 4];
                    accA[0][2*q]   = ffma2(a01, bb.x, accA[0][2*q]);
                    accB[0][2*q]   = ffma2(s01, bb.x, accB[0][2*q]);
                    accA[1][2*q]   = ffma2(a23, bb.x, accA[1][2*q]);
                    accB[1][2*q]   = ffma2(s23, bb.x, accB[1][2*q]);
                    accA[0][2*q+1] = ffma2(a01, bb.y, accA[0][2*q+1]);
                    accB[0][2*q+1] = ffma2(s01, bb.y, accB[0][2*q+1]);
                    accA[1][2*q+1] = ffma2(a23, bb.y, accA[1][2*q+1]);
                    accB[1][2*q+1] = ffma2(s23, bb.y, accB[1][2*q+1]);
                }
            }
            // ---- finish staging for kc+1 ----
            if (kc < 15) {
#pragma unroll
                for (int q = 0; q < 8; q++)
                    Bs[buf ^ 1][bhalf * 8 + q][brow] = bq[q];
                cp_wait0();
            }
            __syncthreads();
        }

        // ---- epilogue: d = fl(fl(zz+ee) - 2*dot), lowest-index tiebreak ----
        // accA[tp][jp] = { dot(t2tp, c2jp), dot(t2tp+1, c2jp+1) }
        // accB[tp][jp] = { dot(t2tp+1, c2jp), dot(t2tp, c2jp+1) }
#pragma unroll
        for (int jp = 0; jp < 8; jp++) {
            int nA = n0 + tx * 16 + 2 * jp;
            int nB = nA + 1;
            float eA = g_ee[nA], eB = g_ee[nB];
#pragma unroll
            for (int tp = 0; tp < 2; tp++) {
                int i0i = 2 * tp, i1i = 2 * tp + 1;
                float2 va = *(float2*)&accA[tp][jp];
                float2 vb = *(float2*)&accB[tp][jp];
                {   // (t_even, c_even)
                    float d = __fadd_rn(__fadd_rn(tzz[i0i], eA), -2.0f * va.x);
                    if (d < best[i0i] || (d == best[i0i] && nA < bidx[i0i])) {
                        best[i0i] = d; bidx[i0i] = nA;
                    }
                }
                {   // (t_odd, c_odd)
                    float d = __fadd_rn(__fadd_rn(tzz[i1i], eB), -2.0f * va.y);
                    if (d < best[i1i] || (d == best[i1i] && nB < bidx[i1i])) {
                        best[i1i] = d; bidx[i1i] = nB;
                    }
                }
                {   // (t_odd, c_even)
                    float d = __fadd_rn(__fadd_rn(tzz[i1i], eA), -2.0f * vb.x);
                    if (d < best[i1i] || (d == best[i1i] && nA < bidx[i1i])) {
                        best[i1i] = d; bidx[i1i] = nA;
                    }
                }
                {   // (t_even, c_odd)
                    float d = __fadd_rn(__fadd_rn(tzz[i0i], eB), -2.0f * vb.y);
                    if (d < best[i0i] || (d == best[i0i] && nB < bidx[i0i])) {
                        best[i0i] = d; bidx[i0i] = nB;
                    }
                }
            }
        }
    }

    // ---- cross-thread reduction over tx (8 candidates per token) ----
    __syncthreads();
    float* rv = (float*)smem_raw;             // [128][8] = 4KB
    int*   ri = (int*)(smem_raw + 4096);      // [128][8] = 4KB
#pragma unroll
    for (int i = 0; i < 4; i++) {
        rv[(ty * 4 + i) * 8 + tx] = best[i];
        ri[(ty * 4 + i) * 8 + tx] = bidx[i];
    }
    __syncthreads();
    if (tid < 128) {
        float bv = rv[tid * 8 + 0];
        int   bi = ri[tid * 8 + 0];
#pragma unroll
        for (int x = 1; x < 8; x++) {
            float v = rv[tid * 8 + x];
            int   id = ri[tid * 8 + x];
            if (v < bv || (v == bv && id < bi)) { bv = v; bi = id; }
        }
        int t = t0 + tid;
        g_idx[t] = bi;
        out[OFF_IDX + t] = (float)bi;
        out[OFF_SAMP + bi] = 1.0f;   // all writers store 1.0f — benign race
    }
}

// ---------------------------------------------------------------------------
__global__ void zq_kernel(const float* __restrict__ z,
                          const float* __restrict__ emb,
                          float* __restrict__ out) {
    __shared__ int sidx[32];
    __shared__ double red[256];
    int tid = threadIdx.x;
    int t0 = blockIdx.x * 32;
    int b = t0 >> 15, s0 = t0 & 32767;
    if (tid < 32) sidx[tid] = g_idx[t0 + tid];
    __syncthreads();
    size_t zbase = ((size_t)b << 23) + s0;
    double acc = 0.0;
    for (int rep = 0; rep < 32; rep++) {
        int lin = rep * 256 + tid;
        int c = lin >> 5;
        int tok = lin & 31;
        float q = emb[(size_t)sidx[tok] * EDIM + c];
        size_t addr = zbase + ((size_t)c << 15) + tok;
        float zv = z[addr];
        out[OFF_ZQ + addr] = q;
        float d = q - zv;
        acc += (double)d * (double)d;
    }
    red[tid] = acc;
    __syncthreads();
    for (int s = 128; s > 0; s >>= 1) {
        if (tid < s) red[tid] += red[tid + s];
        __syncthreads();
    }
    if (tid == 0) atomicAdd(&g_loss_acc, red[0]);
}

// ---------------------------------------------------------------------------
__global__ void __launch_bounds__(256)
cd_kernel(const float* __restrict__ emb) {
    __shared__ float As[16][128];
    __shared__ float Bs[16][128];
    int tid = threadIdx.x;
    int tx = tid & 15, ty = tid >> 4;
    int i0 = blockIdx.y * 128, j0 = blockIdx.x * 128;

    float acc[8][8];
#pragma unroll
    for (int i = 0; i < 8; i++)
#pragma unroll
        for (int j = 0; j < 8; j++) acc[i][j] = 0.0f;

    for (int kc = 0; kc < 16; kc++) {
        int k0 = kc * 16;
        __syncthreads();
        {
            int n = tid & 127;
            int qb = (tid >> 7) * 2;
#pragma unroll
            for (int w = 0; w < 2; w++) {
                int q = qb + w;
                float4 v = *(const float4*)(emb + (size_t)(i0 + n) * EDIM + k0 + q * 4);
                As[q * 4 + 0][n] = v.x; As[q * 4 + 1][n] = v.y;
                As[q * 4 + 2][n] = v.z; As[q * 4 + 3][n] = v.w;
                float4 u = *(const float4*)(emb + (size_t)(j0 + n) * EDIM + k0 + q * 4);
                Bs[q * 4 + 0][n] = u.x; Bs[q * 4 + 1][n] = u.y;
                Bs[q * 4 + 2][n] = u.z; Bs[q * 4 + 3][n] = u.w;
            }
        }
        __syncthreads();
#pragma unroll
        for (int kk = 0; kk < 16; kk++) {
            float a[8], bb[8];
            float4 a0 = *(float4*)&As[kk][ty * 8];
            float4 a1 = *(float4*)&As[kk][ty * 8 + 4];
            a[0] = a0.x; a[1] = a0.y; a[2] = a0.z; a[3] = a0.w;
            a[4] = a1.x; a[5] = a1.y; a[6] = a1.z; a[7] = a1.w;
            float4 b0 = *(float4*)&Bs[kk][tx * 8];
            float4 b1 = *(float4*)&Bs[kk][tx * 8 + 4];
            bb[0] = b0.x; bb[1] = b0.y; bb[2] = b0.z; bb[3] = b0.w;
            bb[4] = b1.x; bb[5] = b1.y; bb[6] = b1.z; bb[7] = b1.w;
#pragma unroll
            for (int i = 0; i < 8; i++)
#pragma unroll
                for (int j = 0; j < 8; j++)
                    acc[i][j] = fmaf(a[i], bb[j], acc[i][j]);
        }
    }
#pragma unroll
    for (int i = 0; i < 8; i++) {
        int gi = i0 + ty * 8 + i;
        float ei = g_ee[gi];
#pragma unroll
        for (int j = 0; j < 8; j++) {
            int gj = j0 + tx * 8 + j;
            float d = __fadd_rn(__fadd_rn(ei, g_ee[gj]), -2.0f * acc[i][j]);
            g_cd[(size_t)gi * NE + gj] = d;
        }
    }
}

__global__ void cdstats_kernel() {
    __shared__ float  s1[256], s2[256];
    __shared__ double ds[256], dq[256];
    int r = blockIdx.x, tid = threadIdx.x;
    const float* row = g_cd + (size_t)r * NE;
    float a = 3.4e38f, b2 = 3.4e38f;
    double sm = 0.0, sq = 0.0;
    for (int j = tid; j < NE; j += 256) {
        float v = row[j];
        sm += v;
        sq += (double)v * v;
        if (v < a) { b2 = a; a = v; }
        else if (v < b2) { b2 = v; }
    }
    s1[tid] = a; s2[tid] = b2; ds[tid] = sm; dq[tid] = sq;
    __syncthreads();
    for (int s = 128; s > 0; s >>= 1) {
        if (tid < s) {
            float x1 = s1[tid], x2 = s2[tid];
            float y1 = s1[tid + s], y2 = s2[tid + s];
            s1[tid] = fminf(x1, y1);
            s2[tid] = fminf(fmaxf(x1, y1), fminf(x2, y2));
            ds[tid] += ds[tid + s];
            dq[tid] += dq[tid + s];
        }
        __syncthreads();
    }
    if (tid == 0) {
        atomicAdd(&g_min2_acc, (double)s2[0]);
        double S = ds[0], Q = dq[0];
        double var = (Q - S * S / 1024.0) / 1023.0;
        atomicAdd(&g_var_acc, var);
    }
}

__global__ void fin_kernel(float* __restrict__ out) {
    float m = (float)(g_loss_acc / 16777216.0);
    out[OFF_LOSS] = 0.2f * m + m;
    out[OFF_MCD] = (float)(g_min2_acc / 1024.0);
    out[OFF_MCV] = (float)(g_var_acc / 1024.0);
}

// ---------------------------------------------------------------------------
extern "C" void kernel_launch(void* const* d_in, const int* in_sizes, int n_in,
                              void* d_out, int out_size) {
    const float* z   = (const float*)d_in[0];
    const float* emb = (const float*)d_in[1];
    float* out = (float*)d_out;

    cudaFuncSetAttribute(dist_kernel,
                         cudaFuncAttributeMaxDynamicSharedMemorySize, 32768);

    init_kernel<<<8, 256>>>(out);
    ee_kernel<<<4, 256>>>(emb);
    zz_kernel<<<256, 256>>>(z);
    dist_kernel<<<512, 256, 32768>>>(z, emb, out);
    zq_kernel<<<2048, 256>>>(z, emb, out);
    cd_kernel<<<dim3(8, 8), 256>>>(emb);
    cdstats_kernel<<<1024, 256>>>();
    fin_kernel<<<1, 1>>>(out);
}

// round 6
// speedup vs baseline: 2.2925x; 2.2925x over previous
#include <cuda_runtime.h>

#define NTOK 65536
#define EDIM 256
#define NE   1024

#define OFF_ZQ   0
#define OFF_LOSS 16777216
#define OFF_IDX  16777217
#define OFF_SAMP 16842753
#define OFF_MCD  16844801
#define OFF_MCV  16844802

typedef unsigned long long ull;

static __device__ float  g_zz[NTOK];
static __device__ float  g_ee[NE];
static __device__ int    g_idx[NTOK];
static __device__ float  g_cd[NE * NE];
static __device__ double g_loss_acc;
static __device__ double g_min2_acc;
static __device__ double g_var_acc;

// Packed dual-fp32 FMA (Blackwell; PTX-only)
__device__ __forceinline__ ull ffma2(ull a, ull b, ull c) {
    ull d;
    asm("fma.rn.f32x2 %0, %1, %2, %3;" : "=l"(d) : "l"(a), "l"(b), "l"(c));
    return d;
}
__device__ __forceinline__ ull swap64(ull a) {
    return (a >> 32) | (a << 32);
}

__device__ __forceinline__ void cp_async16(void* sdst, const void* gsrc) {
    unsigned sa = (unsigned)__cvta_generic_to_shared(sdst);
    asm volatile("cp.async.ca.shared.global [%0], [%1], 16;\n" ::
                 "r"(sa), "l"(gsrc));
}
__device__ __forceinline__ void cp_commit() {
    asm volatile("cp.async.commit_group;\n");
}
__device__ __forceinline__ void cp_wait0() {
    asm volatile("cp.async.wait_group 0;\n" ::: "memory");
}

// ---------------------------------------------------------------------------
__global__ void init_kernel(float* __restrict__ out) {
    int i = blockIdx.x * blockDim.x + threadIdx.x;
    if (i < 2048) out[OFF_SAMP + i] = 0.0f;
    if (i == 0) { g_loss_acc = 0.0; g_min2_acc = 0.0; g_var_acc = 0.0; }
}

__global__ void ee_kernel(const float* __restrict__ emb) {
    int n = blockIdx.x * blockDim.x + threadIdx.x;
    if (n >= NE) return;
    const float* r = emb + (size_t)n * EDIM;
    float acc = 0.0f;
    for (int c = 0; c < EDIM; c++) { float v = r[c]; acc = fmaf(v, v, acc); }
    g_ee[n] = acc;
}

__global__ void zz_kernel(const float* __restrict__ z) {
    int t = blockIdx.x * blockDim.x + threadIdx.x;
    int b = t >> 15, s = t & 32767;
    const float* base = z + ((size_t)b << 23) + s;
    float acc = 0.0f;
#pragma unroll 8
    for (int c = 0; c < EDIM; c++) {
        float v = base[(size_t)c << 15];
        acc = fmaf(v, v, acc);
    }
    g_zz[t] = acc;
}

// ---------------------------------------------------------------------------
// Distance GEMM + argmin. Block tile: 128 tokens x 128 codes (8 nt tiles).
// 256 threads: tx=tid&7 owns codes {q*32 + tx*4 .. +3 | q=0..3} (chunk-
// interleaved so each q-step's 8 tx lanes read CONTIGUOUS 128B from smem ->
// conflict-free LDS.128; this is the fix for the R5 4-way bank conflict at
// 64B stride). ty=tid>>3 owns 4 contiguous tokens. Natural-pair FFMA2 with
// half-swapped A for off-diagonal combos. Numerics bit-identical to R2-R5.
__global__ void __launch_bounds__(256, 2)
dist_kernel(const float* __restrict__ z, const float* __restrict__ emb,
            float* __restrict__ out) {
    extern __shared__ char smem_raw[];
    // [0    , 16384): As[2][16][128] float  (A: z tile, k-major)
    // [16384, 32768): Bs[2][16][128] float  (B: emb tile, [k][code])
    float (*As)[16][128] = (float(*)[16][128])smem_raw;
    float (*Bs)[16][128] = (float(*)[16][128])(smem_raw + 16384);

    int tid = threadIdx.x;
    int tx = tid & 7;        // code group
    int ty = tid >> 3;       // token group
    int t0 = blockIdx.x * 128;
    int b = t0 >> 15, s0 = t0 & 32767;
    const float* zb = z + ((size_t)b << 23) + s0;
    // B staging: thread stages 8 floats of one emb row
    int brow  = tid & 127;
    int bhalf = tid >> 7;

    float tzz[4];
#pragma unroll
    for (int i = 0; i < 4; i++) tzz[i] = g_zz[t0 + ty * 4 + i];

    float best[4];
    int   bidx[4];
#pragma unroll
    for (int i = 0; i < 4; i++) { best[i] = 3.4e38f; bidx[i] = 0; }

    for (int nt = 0; nt < 8; nt++) {
        int n0 = nt * 128;
        const float* bsrc = emb + (size_t)(n0 + brow) * EDIM + bhalf * 8;

        ull accA[2][8], accB[2][8];
#pragma unroll
        for (int p = 0; p < 2; p++)
#pragma unroll
            for (int j = 0; j < 8; j++) { accA[p][j] = 0ull; accB[p][j] = 0ull; }

        float bq[8];

        // ---- prologue: stage kc=0 into buffer 0 ----
        {
            float4 v0 = *(const float4*)(bsrc);
            float4 v1 = *(const float4*)(bsrc + 4);
            bq[0]=v0.x; bq[1]=v0.y; bq[2]=v0.z; bq[3]=v0.w;
            bq[4]=v1.x; bq[5]=v1.y; bq[6]=v1.z; bq[7]=v1.w;
#pragma unroll
            for (int c = 0; c < 2; c++) {
                int lin = c * 256 + tid;
                int row = lin >> 5, col = (lin & 31) * 4;
                cp_async16(&As[0][row][col], zb + ((size_t)row << 15) + col);
            }
            cp_commit();
#pragma unroll
            for (int q = 0; q < 8; q++)
                Bs[0][bhalf * 8 + q][brow] = bq[q];
            cp_wait0();
        }
        __syncthreads();

        for (int kc = 0; kc < 16; kc++) {
            int buf = kc & 1;
            // ---- issue staging for kc+1 (latency hidden under compute) ----
            if (kc < 15) {
                const float* p1 = bsrc + (kc + 1) * 16;
                float4 v0 = *(const float4*)(p1);
                float4 v1 = *(const float4*)(p1 + 4);
                bq[0]=v0.x; bq[1]=v0.y; bq[2]=v0.z; bq[3]=v0.w;
                bq[4]=v1.x; bq[5]=v1.y; bq[6]=v1.z; bq[7]=v1.w;
#pragma unroll
                for (int c = 0; c < 2; c++) {
                    int lin = c * 256 + tid;
                    int row = lin >> 5, col = (lin & 31) * 4;
                    cp_async16(&As[buf ^ 1][row][col],
                               zb + ((size_t)((kc + 1) * 16 + row) << 15) + col);
                }
                cp_commit();
            }
            // ---- compute kc from buf ----
#pragma unroll
            for (int kk = 0; kk < 16; kk++) {
                // A: 4 tokens as 2 natural ull pairs + 2 half-swaps
                ulonglong2 av = *(const ulonglong2*)&As[buf][kk][ty * 4];
                ull a01 = av.x, a23 = av.y;
                ull s01 = swap64(a01), s23 = swap64(a23);
                // B: 4 LDS.128, chunk (q*8+tx) -> contiguous per phase
#pragma unroll
                for (int q = 0; q < 4; q++) {
                    ulonglong2 bb =
                        *(const ulonglong2*)&Bs[buf][kk][(q * 8 + tx) * 4];
                    accA[0][2*q]   = ffma2(a01, bb.x, accA[0][2*q]);
                    accB[0][2*q]   = ffma2(s01, bb.x, accB[0][2*q]);
                    accA[1][2*q]   = ffma2(a23, bb.x, accA[1][2*q]);
                    accB[1][2*q]   = ffma2(s23, bb.x, accB[1][2*q]);
                    accA[0][2*q+1] = ffma2(a01, bb.y, accA[0][2*q+1]);
                    accB[0][2*q+1] = ffma2(s01, bb.y, accB[0][2*q+1]);
                    accA[1][2*q+1] = ffma2(a23, bb.y, accA[1][2*q+1]);
                    accB[1][2*q+1] = ffma2(s23, bb.y, accB[1][2*q+1]);
                }
            }
            // ---- finish staging for kc+1 ----
            if (kc < 15) {
#pragma unroll
                for (int q = 0; q < 8; q++)
                    Bs[buf ^ 1][bhalf * 8 + q][brow] = bq[q];
                cp_wait0();
            }
            __syncthreads();
        }

        // ---- epilogue: d = fl(fl(zz+ee) - 2*dot), lowest-index tiebreak ----
        // accA[tp][2q+h] = { dot(t2tp, cBase), dot(t2tp+1, cBase+1) }
        // accB[tp][2q+h] = { dot(t2tp+1, cBase), dot(t2tp, cBase+1) }
        // where cBase = n0 + q*32 + tx*4 + 2h
#pragma unroll
        for (int q = 0; q < 4; q++) {
#pragma unroll
            for (int h = 0; h < 2; h++) {
                int nA = n0 + q * 32 + tx * 4 + 2 * h;
                int nB = nA + 1;
                float eA = g_ee[nA], eB = g_ee[nB];
#pragma unroll
                for (int tp = 0; tp < 2; tp++) {
                    int i0i = 2 * tp, i1i = 2 * tp + 1;
                    float2 va = *(float2*)&accA[tp][2 * q + h];
                    float2 vb = *(float2*)&accB[tp][2 * q + h];
                    {   // (t_even, c_even)
                        float d = __fadd_rn(__fadd_rn(tzz[i0i], eA), -2.0f * va.x);
                        if (d < best[i0i] || (d == best[i0i] && nA < bidx[i0i])) {
                            best[i0i] = d; bidx[i0i] = nA;
                        }
                    }
                    {   // (t_odd, c_odd)
                        float d = __fadd_rn(__fadd_rn(tzz[i1i], eB), -2.0f * va.y);
                        if (d < best[i1i] || (d == best[i1i] && nB < bidx[i1i])) {
                            best[i1i] = d; bidx[i1i] = nB;
                        }
                    }
                    {   // (t_odd, c_even)
                        float d = __fadd_rn(__fadd_rn(tzz[i1i], eA), -2.0f * vb.x);
                        if (d < best[i1i] || (d == best[i1i] && nA < bidx[i1i])) {
                            best[i1i] = d; bidx[i1i] = nA;
                        }
                    }
                    {   // (t_even, c_odd)
                        float d = __fadd_rn(__fadd_rn(tzz[i0i], eB), -2.0f * vb.y);
                        if (d < best[i0i] || (d == best[i0i] && nB < bidx[i0i])) {
                            best[i0i] = d; bidx[i0i] = nB;
                        }
                    }
                }
            }
        }
    }

    // ---- cross-thread reduction over tx (8 candidates per token) ----
    __syncthreads();
    float* rv = (float*)smem_raw;             // [128][8] = 4KB
    int*   ri = (int*)(smem_raw + 4096);      // [128][8] = 4KB
#pragma unroll
    for (int i = 0; i < 4; i++) {
        rv[(ty * 4 + i) * 8 + tx] = best[i];
        ri[(ty * 4 + i) * 8 + tx] = bidx[i];
    }
    __syncthreads();
    if (tid < 128) {
        float bv = rv[tid * 8 + 0];
        int   bi = ri[tid * 8 + 0];
#pragma unroll
        for (int x = 1; x < 8; x++) {
            float v = rv[tid * 8 + x];
            int   id = ri[tid * 8 + x];
            if (v < bv || (v == bv && id < bi)) { bv = v; bi = id; }
        }
        int t = t0 + tid;
        g_idx[t] = bi;
        out[OFF_IDX + t] = (float)bi;
        out[OFF_SAMP + bi] = 1.0f;   // all writers store 1.0f — benign race
    }
}

// ---------------------------------------------------------------------------
__global__ void zq_kernel(const float* __restrict__ z,
                          const float* __restrict__ emb,
                          float* __restrict__ out) {
    __shared__ int sidx[32];
    __shared__ double red[256];
    int tid = threadIdx.x;
    int t0 = blockIdx.x * 32;
    int b = t0 >> 15, s0 = t0 & 32767;
    if (tid < 32) sidx[tid] = g_idx[t0 + tid];
    __syncthreads();
    size_t zbase = ((size_t)b << 23) + s0;
    double acc = 0.0;
    for (int rep = 0; rep < 32; rep++) {
        int lin = rep * 256 + tid;
        int c = lin >> 5;
        int tok = lin & 31;
        float q = emb[(size_t)sidx[tok] * EDIM + c];
        size_t addr = zbase + ((size_t)c << 15) + tok;
        float zv = z[addr];
        out[OFF_ZQ + addr] = q;
        float d = q - zv;
        acc += (double)d * (double)d;
    }
    red[tid] = acc;
    __syncthreads();
    for (int s = 128; s > 0; s >>= 1) {
        if (tid < s) red[tid] += red[tid + s];
        __syncthreads();
    }
    if (tid == 0) atomicAdd(&g_loss_acc, red[0]);
}

// ---------------------------------------------------------------------------
__global__ void __launch_bounds__(256)
cd_kernel(const float* __restrict__ emb) {
    __shared__ float As[16][128];
    __shared__ float Bs[16][128];
    int tid = threadIdx.x;
    int tx = tid & 15, ty = tid >> 4;
    int i0 = blockIdx.y * 128, j0 = blockIdx.x * 128;

    float acc[8][8];
#pragma unroll
    for (int i = 0; i < 8; i++)
#pragma unroll
        for (int j = 0; j < 8; j++) acc[i][j] = 0.0f;

    for (int kc = 0; kc < 16; kc++) {
        int k0 = kc * 16;
        __syncthreads();
        {
            int n = tid & 127;
            int qb = (tid >> 7) * 2;
#pragma unroll
            for (int w = 0; w < 2; w++) {
                int q = qb + w;
                float4 v = *(const float4*)(emb + (size_t)(i0 + n) * EDIM + k0 + q * 4);
                As[q * 4 + 0][n] = v.x; As[q * 4 + 1][n] = v.y;
                As[q * 4 + 2][n] = v.z; As[q * 4 + 3][n] = v.w;
                float4 u = *(const float4*)(emb + (size_t)(j0 + n) * EDIM + k0 + q * 4);
                Bs[q * 4 + 0][n] = u.x; Bs[q * 4 + 1][n] = u.y;
                Bs[q * 4 + 2][n] = u.z; Bs[q * 4 + 3][n] = u.w;
            }
        }
        __syncthreads();
#pragma unroll
        for (int kk = 0; kk < 16; kk++) {
            float a[8], bb[8];
            float4 a0 = *(float4*)&As[kk][ty * 8];
            float4 a1 = *(float4*)&As[kk][ty * 8 + 4];
            a[0] = a0.x; a[1] = a0.y; a[2] = a0.z; a[3] = a0.w;
            a[4] = a1.x; a[5] = a1.y; a[6] = a1.z; a[7] = a1.w;
            float4 b0 = *(float4*)&Bs[kk][tx * 8];
            float4 b1 = *(float4*)&Bs[kk][tx * 8 + 4];
            bb[0] = b0.x; bb[1] = b0.y; bb[2] = b0.z; bb[3] = b0.w;
            bb[4] = b1.x; bb[5] = b1.y; bb[6] = b1.z; bb[7] = b1.w;
#pragma unroll
            for (int i = 0; i < 8; i++)
#pragma unroll
                for (int j = 0; j < 8; j++)
                    acc[i][j] = fmaf(a[i], bb[j], acc[i][j]);
        }
    }
#pragma unroll
    for (int i = 0; i < 8; i++) {
        int gi = i0 + ty * 8 + i;
        float ei = g_ee[gi];
#pragma unroll
        for (int j = 0; j < 8; j++) {
            int gj = j0 + tx * 8 + j;
            float d = __fadd_rn(__fadd_rn(ei, g_ee[gj]), -2.0f * acc[i][j]);
            g_cd[(size_t)gi * NE + gj] = d;
        }
    }
}

__global__ void cdstats_kernel() {
    __shared__ float  s1[256], s2[256];
    __shared__ double ds[256], dq[256];
    int r = blockIdx.x, tid = threadIdx.x;
    const float* row = g_cd + (size_t)r * NE;
    float a = 3.4e38f, b2 = 3.4e38f;
    double sm = 0.0, sq = 0.0;
    for (int j = tid; j < NE; j += 256) {
        float v = row[j];
        sm += v;
        sq += (double)v * v;
        if (v < a) { b2 = a; a = v; }
        else if (v < b2) { b2 = v; }
    }
    s1[tid] = a; s2[tid] = b2; ds[tid] = sm; dq[tid] = sq;
    __syncthreads();
    for (int s = 128; s > 0; s >>= 1) {
        if (tid < s) {
            float x1 = s1[tid], x2 = s2[tid];
            float y1 = s1[tid + s], y2 = s2[tid + s];
            s1[tid] = fminf(x1, y1);
            s2[tid] = fminf(fmaxf(x1, y1), fminf(x2, y2));
            ds[tid] += ds[tid + s];
            dq[tid] += dq[tid + s];
        }
        __syncthreads();
    }
    if (tid == 0) {
        atomicAdd(&g_min2_acc, (double)s2[0]);
        double S = ds[0], Q = dq[0];
        double var = (Q - S * S / 1024.0) / 1023.0;
        atomicAdd(&g_var_acc, var);
    }
}

__global__ void fin_kernel(float* __restrict__ out) {
    float m = (float)(g_loss_acc / 16777216.0);
    out[OFF_LOSS] = 0.2f * m + m;
    out[OFF_MCD] = (float)(g_min2_acc / 1024.0);
    out[OFF_MCV] = (float)(g_var_acc / 1024.0);
}

// ---------------------------------------------------------------------------
extern "C" void kernel_launch(void* const* d_in, const int* in_sizes, int n_in,
                              void* d_out, int out_size) {
    const float* z   = (const float*)d_in[0];
    const float* emb = (const float*)d_in[1];
    float* out = (float*)d_out;

    cudaFuncSetAttribute(dist_kernel,
                         cudaFuncAttributeMaxDynamicSharedMemorySize, 32768);

    init_kernel<<<8, 256>>>(out);
    ee_kernel<<<4, 256>>>(emb);
    zz_kernel<<<256, 256>>>(z);
    dist_kernel<<<512, 256, 32768>>>(z, emb, out);
    zq_kernel<<<2048, 256>>>(z, emb, out);
    cd_kernel<<<dim3(8, 8), 256>>>(emb);
    cdstats_kernel<<<1024, 256>>>();
    fin_kernel<<<1, 1>>>(out);
}

// round 7
// speedup vs baseline: 2.4379x; 1.0634x over previous
#include <cuda_runtime.h>

#define NTOK 65536
#define EDIM 256
#define NE   1024

#define OFF_ZQ   0
#define OFF_LOSS 16777216
#define OFF_IDX  16777217
#define OFF_SAMP 16842753
#define OFF_MCD  16844801
#define OFF_MCV  16844802

typedef unsigned long long ull;

static __device__ float  g_zz[NTOK];
static __device__ float  g_ee[NE];
static __device__ int    g_idx[NTOK];
static __device__ float  g_cd[NE * NE];
static __device__ double g_loss_acc;
static __device__ double g_min2_acc;
static __device__ double g_var_acc;

// Packed dual-fp32 FMA (Blackwell; PTX-only)
__device__ __forceinline__ ull ffma2(ull a, ull b, ull c) {
    ull d;
    asm("fma.rn.f32x2 %0, %1, %2, %3;" : "=l"(d) : "l"(a), "l"(b), "l"(c));
    return d;
}
__device__ __forceinline__ ull swap64(ull a) {
    return (a >> 32) | (a << 32);
}

__device__ __forceinline__ void cp_async16(void* sdst, const void* gsrc) {
    unsigned sa = (unsigned)__cvta_generic_to_shared(sdst);
    asm volatile("cp.async.ca.shared.global [%0], [%1], 16;\n" ::
                 "r"(sa), "l"(gsrc));
}
__device__ __forceinline__ void cp_commit() {
    asm volatile("cp.async.commit_group;\n");
}
template <int N>
__device__ __forceinline__ void cp_wait() {
    asm volatile("cp.async.wait_group %0;\n" :: "n"(N) : "memory");
}

// ---------------------------------------------------------------------------
__global__ void init_kernel(float* __restrict__ out) {
    int i = blockIdx.x * blockDim.x + threadIdx.x;
    if (i < 2048) out[OFF_SAMP + i] = 0.0f;
    if (i == 0) { g_loss_acc = 0.0; g_min2_acc = 0.0; g_var_acc = 0.0; }
}

__global__ void ee_kernel(const float* __restrict__ emb) {
    int n = blockIdx.x * blockDim.x + threadIdx.x;
    if (n >= NE) return;
    const float* r = emb + (size_t)n * EDIM;
    float acc = 0.0f;
    for (int c = 0; c < EDIM; c++) { float v = r[c]; acc = fmaf(v, v, acc); }
    g_ee[n] = acc;
}

__global__ void zz_kernel(const float* __restrict__ z) {
    int t = blockIdx.x * blockDim.x + threadIdx.x;
    int b = t >> 15, s = t & 32767;
    const float* base = z + ((size_t)b << 23) + s;
    float acc = 0.0f;
#pragma unroll 8
    for (int c = 0; c < EDIM; c++) {
        float v = base[(size_t)c << 15];
        acc = fmaf(v, v, acc);
    }
    g_zz[t] = acc;
}

// ---------------------------------------------------------------------------
// Distance GEMM + argmin. Block tile: 128 tokens x 128 codes (8 nt tiles).
// 256 threads: ty=tid>>4 owns 8 tokens (4 natural ull pairs + swaps),
// tx=tid&15 owns 8 codes as chunks {tx*4..+3} and {64+tx*4..+3} (contiguous
// per 8-lane phase -> conflict-free LDS.128). Per warp-kk: 4 LDS.128 (16
// crossbar cyc) vs 32 FFMA2 (64 fma cyc) -> crossbar no longer binds.
// A staged via 3-buffer cp.async (prefetch distance 2) to cover z DRAM
// latency; B (L2-resident emb) staged distance 1 via regs+STS.
// Numerics bit-identical to R2-R6 (per-(t,n) sequential k, same epilogue).
__global__ void __launch_bounds__(256, 2)
dist_kernel(const float* __restrict__ z, const float* __restrict__ emb,
            float* __restrict__ out) {
    extern __shared__ char smem_raw[];
    // [0    , 24576): As[3][16][128] float  (A: z tile, k-major, 3-stage)
    // [24576, 40960): Bs[2][16][128] float  (B: emb tile, [k][code], 2-stage)
    float (*As)[16][128] = (float(*)[16][128])smem_raw;
    float (*Bs)[16][128] = (float(*)[16][128])(smem_raw + 24576);

    int tid = threadIdx.x;
    int tx = tid & 15;       // code group
    int ty = tid >> 4;       // token group (8 tokens)
    int t0 = blockIdx.x * 128;
    int b = t0 >> 15, s0 = t0 & 32767;
    const float* zb = z + ((size_t)b << 23) + s0;
    // B staging: thread stages 8 floats of one emb row
    int brow  = tid & 127;
    int bhalf = tid >> 7;

    float tzz[8];
#pragma unroll
    for (int i = 0; i < 8; i++) tzz[i] = g_zz[t0 + ty * 8 + i];

    float best[8];
    int   bidx[8];
#pragma unroll
    for (int i = 0; i < 8; i++) { best[i] = 3.4e38f; bidx[i] = 0; }

    for (int nt = 0; nt < 8; nt++) {
        int n0 = nt * 128;
        const float* bsrc = emb + (size_t)(n0 + brow) * EDIM + bhalf * 8;

        ull accA[4][4], accB[4][4];
#pragma unroll
        for (int p = 0; p < 4; p++)
#pragma unroll
            for (int j = 0; j < 4; j++) { accA[p][j] = 0ull; accB[p][j] = 0ull; }

        float bq[8];

        // ---- prologue: A kc=0,1 in flight; B kc=0 staged ----
        {
#pragma unroll
            for (int c = 0; c < 2; c++) {
                int lin = c * 256 + tid;
                int row = lin >> 5, col = (lin & 31) * 4;
                cp_async16(&As[0][row][col], zb + ((size_t)row << 15) + col);
            }
            cp_commit();
            float4 v0 = *(const float4*)(bsrc);
            float4 v1 = *(const float4*)(bsrc + 4);
            bq[0]=v0.x; bq[1]=v0.y; bq[2]=v0.z; bq[3]=v0.w;
            bq[4]=v1.x; bq[5]=v1.y; bq[6]=v1.z; bq[7]=v1.w;
#pragma unroll
            for (int c = 0; c < 2; c++) {
                int lin = c * 256 + tid;
                int row = lin >> 5, col = (lin & 31) * 4;
                cp_async16(&As[1][row][col],
                           zb + ((size_t)(16 + row) << 15) + col);
            }
            cp_commit();
#pragma unroll
            for (int q = 0; q < 8; q++)
                Bs[0][bhalf * 8 + q][brow] = bq[q];
            cp_wait<1>();   // As[0] ready
        }
        __syncthreads();

        for (int kc = 0; kc < 16; kc++) {
            int ab = kc % 3;
            int bb = kc & 1;
            // ---- B global load for kc+1 (L2-resident) ----
            if (kc < 15) {
                const float* p1 = bsrc + (kc + 1) * 16;
                float4 v0 = *(const float4*)(p1);
                float4 v1 = *(const float4*)(p1 + 4);
                bq[0]=v0.x; bq[1]=v0.y; bq[2]=v0.z; bq[3]=v0.w;
                bq[4]=v1.x; bq[5]=v1.y; bq[6]=v1.z; bq[7]=v1.w;
            }
            // ---- A cp.async for kc+2 (distance-2 prefetch) ----
            if (kc < 14) {
                int dst = (kc + 2) % 3;
#pragma unroll
                for (int c = 0; c < 2; c++) {
                    int lin = c * 256 + tid;
                    int row = lin >> 5, col = (lin & 31) * 4;
                    cp_async16(&As[dst][row][col],
                               zb + ((size_t)((kc + 2) * 16 + row) << 15) + col);
                }
                cp_commit();
            }
            // ---- compute kc ----
#pragma unroll
            for (int kk = 0; kk < 16; kk++) {
                ulonglong2 av0 = *(const ulonglong2*)&As[ab][kk][ty * 8];
                ulonglong2 av1 = *(const ulonglong2*)&As[ab][kk][ty * 8 + 4];
                ull a0 = av0.x, a1 = av0.y, a2 = av1.x, a3 = av1.y;
                ull s0v = swap64(a0), s1v = swap64(a1);
                ull s2v = swap64(a2), s3v = swap64(a3);
                ulonglong2 bv0 = *(const ulonglong2*)&Bs[bb][kk][tx * 4];
                ulonglong2 bv1 = *(const ulonglong2*)&Bs[bb][kk][64 + tx * 4];
                ull bp0 = bv0.x, bp1 = bv0.y, bp2 = bv1.x, bp3 = bv1.y;
                accA[0][0] = ffma2(a0, bp0, accA[0][0]);
                accB[0][0] = ffma2(s0v, bp0, accB[0][0]);
                accA[1][0] = ffma2(a1, bp0, accA[1][0]);
                accB[1][0] = ffma2(s1v, bp0, accB[1][0]);
                accA[2][0] = ffma2(a2, bp0, accA[2][0]);
                accB[2][0] = ffma2(s2v, bp0, accB[2][0]);
                accA[3][0] = ffma2(a3, bp0, accA[3][0]);
                accB[3][0] = ffma2(s3v, bp0, accB[3][0]);
                accA[0][1] = ffma2(a0, bp1, accA[0][1]);
                accB[0][1] = ffma2(s0v, bp1, accB[0][1]);
                accA[1][1] = ffma2(a1, bp1, accA[1][1]);
                accB[1][1] = ffma2(s1v, bp1, accB[1][1]);
                accA[2][1] = ffma2(a2, bp1, accA[2][1]);
                accB[2][1] = ffma2(s2v, bp1, accB[2][1]);
                accA[3][1] = ffma2(a3, bp1, accA[3][1]);
                accB[3][1] = ffma2(s3v, bp1, accB[3][1]);
                accA[0][2] = ffma2(a0, bp2, accA[0][2]);
                accB[0][2] = ffma2(s0v, bp2, accB[0][2]);
                accA[1][2] = ffma2(a1, bp2, accA[1][2]);
                accB[1][2] = ffma2(s1v, bp2, accB[1][2]);
                accA[2][2] = ffma2(a2, bp2, accA[2][2]);
                accB[2][2] = ffma2(s2v, bp2, accB[2][2]);
                accA[3][2] = ffma2(a3, bp2, accA[3][2]);
                accB[3][2] = ffma2(s3v, bp2, accB[3][2]);
                accA[0][3] = ffma2(a0, bp3, accA[0][3]);
                accB[0][3] = ffma2(s0v, bp3, accB[0][3]);
                accA[1][3] = ffma2(a1, bp3, accA[1][3]);
                accB[1][3] = ffma2(s1v, bp3, accB[1][3]);
                accA[2][3] = ffma2(a2, bp3, accA[2][3]);
                accB[2][3] = ffma2(s2v, bp3, accB[2][3]);
                accA[3][3] = ffma2(a3, bp3, accA[3][3]);
                accB[3][3] = ffma2(s3v, bp3, accB[3][3]);
            }
            // ---- finish staging ----
            if (kc < 15) {
#pragma unroll
                for (int q = 0; q < 8; q++)
                    Bs[bb ^ 1][bhalf * 8 + q][brow] = bq[q];
            }
            if (kc < 14)      cp_wait<1>();   // As[kc+1] done, As[kc+2] may fly
            else if (kc == 14) cp_wait<0>();  // As[15] done
            __syncthreads();
        }

        // ---- epilogue: d = fl(fl(zz+ee) - 2*dot), lowest-index tiebreak ----
        // accA[tp][bp] = { dot(tokE, nBase), dot(tokO, nBase+1) }
        // accB[tp][bp] = { dot(tokO, nBase), dot(tokE, nBase+1) }
        // nBase = n0 + (bp>>1)*64 + tx*4 + 2*(bp&1); tokE = ty*8+2tp
#pragma unroll
        for (int bp = 0; bp < 4; bp++) {
            int nA = n0 + (bp >> 1) * 64 + tx * 4 + 2 * (bp & 1);
            int nB = nA + 1;
            float eA = g_ee[nA], eB = g_ee[nB];
#pragma unroll
            for (int tp = 0; tp < 4; tp++) {
                int iE = 2 * tp, iO = 2 * tp + 1;
                float2 va = *(float2*)&accA[tp][bp];
                float2 vb = *(float2*)&accB[tp][bp];
                {   // (tokE, nA)
                    float d = __fadd_rn(__fadd_rn(tzz[iE], eA), -2.0f * va.x);
                    if (d < best[iE] || (d == best[iE] && nA < bidx[iE])) {
                        best[iE] = d; bidx[iE] = nA;
                    }
                }
                {   // (tokO, nB)
                    float d = __fadd_rn(__fadd_rn(tzz[iO], eB), -2.0f * va.y);
                    if (d < best[iO] || (d == best[iO] && nB < bidx[iO])) {
                        best[iO] = d; bidx[iO] = nB;
                    }
                }
                {   // (tokO, nA)
                    float d = __fadd_rn(__fadd_rn(tzz[iO], eA), -2.0f * vb.x);
                    if (d < best[iO] || (d == best[iO] && nA < bidx[iO])) {
                        best[iO] = d; bidx[iO] = nA;
                    }
                }
                {   // (tokE, nB)
                    float d = __fadd_rn(__fadd_rn(tzz[iE], eB), -2.0f * vb.y);
                    if (d < best[iE] || (d == best[iE] && nB < bidx[iE])) {
                        best[iE] = d; bidx[iE] = nB;
                    }
                }
            }
        }
    }

    // ---- cross-thread reduction over tx (16 candidates per token) ----
    __syncthreads();
    float* rv = (float*)smem_raw;             // [128][16] = 8KB
    int*   ri = (int*)(smem_raw + 8192);      // [128][16] = 8KB
#pragma unroll
    for (int i = 0; i < 8; i++) {
        rv[(ty * 8 + i) * 16 + tx] = best[i];
        ri[(ty * 8 + i) * 16 + tx] = bidx[i];
    }
    __syncthreads();
    if (tid < 128) {
        float bv = rv[tid * 16 + 0];
        int   bi = ri[tid * 16 + 0];
#pragma unroll
        for (int x = 1; x < 16; x++) {
            float v = rv[tid * 16 + x];
            int   id = ri[tid * 16 + x];
            if (v < bv || (v == bv && id < bi)) { bv = v; bi = id; }
        }
        int t = t0 + tid;
        g_idx[t] = bi;
        out[OFF_IDX + t] = (float)bi;
        out[OFF_SAMP + bi] = 1.0f;   // all writers store 1.0f — benign race
    }
}

// ---------------------------------------------------------------------------
__global__ void zq_kernel(const float* __restrict__ z,
                          const float* __restrict__ emb,
                          float* __restrict__ out) {
    __shared__ int sidx[32];
    __shared__ double red[256];
    int tid = threadIdx.x;
    int t0 = blockIdx.x * 32;
    int b = t0 >> 15, s0 = t0 & 32767;
    if (tid < 32) sidx[tid] = g_idx[t0 + tid];
    __syncthreads();
    size_t zbase = ((size_t)b << 23) + s0;
    double acc = 0.0;
    for (int rep = 0; rep < 32; rep++) {
        int lin = rep * 256 + tid;
        int c = lin >> 5;
        int tok = lin & 31;
        float q = emb[(size_t)sidx[tok] * EDIM + c];
        size_t addr = zbase + ((size_t)c << 15) + tok;
        float zv = z[addr];
        out[OFF_ZQ + addr] = q;
        float d = q - zv;
        acc += (double)d * (double)d;
    }
    red[tid] = acc;
    __syncthreads();
    for (int s = 128; s > 0; s >>= 1) {
        if (tid < s) red[tid] += red[tid + s];
        __syncthreads();
    }
    if (tid == 0) atomicAdd(&g_loss_acc, red[0]);
}

// ---------------------------------------------------------------------------
__global__ void __launch_bounds__(256)
cd_kernel(const float* __restrict__ emb) {
    __shared__ float As[16][128];
    __shared__ float Bs[16][128];
    int tid = threadIdx.x;
    int tx = tid & 15, ty = tid >> 4;
    int i0 = blockIdx.y * 128, j0 = blockIdx.x * 128;

    float acc[8][8];
#pragma unroll
    for (int i = 0; i < 8; i++)
#pragma unroll
        for (int j = 0; j < 8; j++) acc[i][j] = 0.0f;

    for (int kc = 0; kc < 16; kc++) {
        int k0 = kc * 16;
        __syncthreads();
        {
            int n = tid & 127;
            int qb = (tid >> 7) * 2;
#pragma unroll
            for (int w = 0; w < 2; w++) {
                int q = qb + w;
                float4 v = *(const float4*)(emb + (size_t)(i0 + n) * EDIM + k0 + q * 4);
                As[q * 4 + 0][n] = v.x; As[q * 4 + 1][n] = v.y;
                As[q * 4 + 2][n] = v.z; As[q * 4 + 3][n] = v.w;
                float4 u = *(const float4*)(emb + (size_t)(j0 + n) * EDIM + k0 + q * 4);
                Bs[q * 4 + 0][n] = u.x; Bs[q * 4 + 1][n] = u.y;
                Bs[q * 4 + 2][n] = u.z; Bs[q * 4 + 3][n] = u.w;
            }
        }
        __syncthreads();
#pragma unroll
        for (int kk = 0; kk < 16; kk++) {
            float a[8], bb[8];
            float4 a0 = *(float4*)&As[kk][ty * 8];
            float4 a1 = *(float4*)&As[kk][ty * 8 + 4];
            a[0] = a0.x; a[1] = a0.y; a[2] = a0.z; a[3] = a0.w;
            a[4] = a1.x; a[5] = a1.y; a[6] = a1.z; a[7] = a1.w;
            float4 b0 = *(float4*)&Bs[kk][tx * 8];
            float4 b1 = *(float4*)&Bs[kk][tx * 8 + 4];
            bb[0] = b0.x; bb[1] = b0.y; bb[2] = b0.z; bb[3] = b0.w;
            bb[4] = b1.x; bb[5] = b1.y; bb[6] = b1.z; bb[7] = b1.w;
#pragma unroll
            for (int i = 0; i < 8; i++)
#pragma unroll
                for (int j = 0; j < 8; j++)
                    acc[i][j] = fmaf(a[i], bb[j], acc[i][j]);
        }
    }
#pragma unroll
    for (int i = 0; i < 8; i++) {
        int gi = i0 + ty * 8 + i;
        float ei = g_ee[gi];
#pragma unroll
        for (int j = 0; j < 8; j++) {
            int gj = j0 + tx * 8 + j;
            float d = __fadd_rn(__fadd_rn(ei, g_ee[gj]), -2.0f * acc[i][j]);
            g_cd[(size_t)gi * NE + gj] = d;
        }
    }
}

__global__ void cdstats_kernel() {
    __shared__ float  s1[256], s2[256];
    __shared__ double ds[256], dq[256];
    int r = blockIdx.x, tid = threadIdx.x;
    const float* row = g_cd + (size_t)r * NE;
    float a = 3.4e38f, b2 = 3.4e38f;
    double sm = 0.0, sq = 0.0;
    for (int j = tid; j < NE; j += 256) {
        float v = row[j];
        sm += v;
        sq += (double)v * v;
        if (v < a) { b2 = a; a = v; }
        else if (v < b2) { b2 = v; }
    }
    s1[tid] = a; s2[tid] = b2; ds[tid] = sm; dq[tid] = sq;
    __syncthreads();
    for (int s = 128; s > 0; s >>= 1) {
        if (tid < s) {
            float x1 = s1[tid], x2 = s2[tid];
            float y1 = s1[tid + s], y2 = s2[tid + s];
            s1[tid] = fminf(x1, y1);
            s2[tid] = fminf(fmaxf(x1, y1), fminf(x2, y2));
            ds[tid] += ds[tid + s];
            dq[tid] += dq[tid + s];
        }
        __syncthreads();
    }
    if (tid == 0) {
        atomicAdd(&g_min2_acc, (double)s2[0]);
        double S = ds[0], Q = dq[0];
        double var = (Q - S * S / 1024.0) / 1023.0;
        atomicAdd(&g_var_acc, var);
    }
}

__global__ void fin_kernel(float* __restrict__ out) {
    float m = (float)(g_loss_acc / 16777216.0);
    out[OFF_LOSS] = 0.2f * m + m;
    out[OFF_MCD] = (float)(g_min2_acc / 1024.0);
    out[OFF_MCV] = (float)(g_var_acc / 1024.0);
}

// ---------------------------------------------------------------------------
extern "C" void kernel_launch(void* const* d_in, const int* in_sizes, int n_in,
                              void* d_out, int out_size) {
    const float* z   = (const float*)d_in[0];
    const float* emb = (const float*)d_in[1];
    float* out = (float*)d_out;

    cudaFuncSetAttribute(dist_kernel,
                         cudaFuncAttributeMaxDynamicSharedMemorySize, 40960);

    init_kernel<<<8, 256>>>(out);
    ee_kernel<<<4, 256>>>(emb);
    zz_kernel<<<256, 256>>>(z);
    dist_kernel<<<512, 256, 40960>>>(z, emb, out);
    zq_kernel<<<2048, 256>>>(z, emb, out);
    cd_kernel<<<dim3(8, 8), 256>>>(emb);
    cdstats_kernel<<<1024, 256>>>();
    fin_kernel<<<1, 1>>>(out);
}

// round 8
// speedup vs baseline: 2.4398x; 1.0008x over previous
#include <cuda_runtime.h>

#define NTOK 65536
#define EDIM 256
#define NE   1024

#define OFF_ZQ   0
#define OFF_LOSS 16777216
#define OFF_IDX  16777217
#define OFF_SAMP 16842753
#define OFF_MCD  16844801
#define OFF_MCV  16844802

typedef unsigned long long ull;

static __device__ float  g_zz[NTOK];
static __device__ float  g_ee[NE];
static __device__ int    g_idx[NTOK];
static __device__ float  g_cd[NE * NE];
static __device__ double g_loss_acc;
static __device__ double g_min2_acc;
static __device__ double g_var_acc;

// Packed dual-fp32 FMA (Blackwell; PTX-only)
__device__ __forceinline__ ull ffma2(ull a, ull b, ull c) {
    ull d;
    asm("fma.rn.f32x2 %0, %1, %2, %3;" : "=l"(d) : "l"(a), "l"(b), "l"(c));
    return d;
}
__device__ __forceinline__ ull swap64(ull a) {
    return (a >> 32) | (a << 32);
}

__device__ __forceinline__ void cp_async16(void* sdst, const void* gsrc) {
    unsigned sa = (unsigned)__cvta_generic_to_shared(sdst);
    asm volatile("cp.async.ca.shared.global [%0], [%1], 16;\n" ::
                 "r"(sa), "l"(gsrc));
}
__device__ __forceinline__ void cp_commit() {
    asm volatile("cp.async.commit_group;\n");
}
template <int N>
__device__ __forceinline__ void cp_wait() {
    asm volatile("cp.async.wait_group %0;\n" :: "n"(N) : "memory");
}

// ---------------------------------------------------------------------------
__global__ void init_kernel(float* __restrict__ out) {
    int i = blockIdx.x * blockDim.x + threadIdx.x;
    if (i < 2048) out[OFF_SAMP + i] = 0.0f;
    if (i == 0) { g_loss_acc = 0.0; g_min2_acc = 0.0; g_var_acc = 0.0; }
}

__global__ void ee_kernel(const float* __restrict__ emb) {
    int n = blockIdx.x * blockDim.x + threadIdx.x;
    if (n >= NE) return;
    const float* r = emb + (size_t)n * EDIM;
    float acc = 0.0f;
    for (int c = 0; c < EDIM; c++) { float v = r[c]; acc = fmaf(v, v, acc); }
    g_ee[n] = acc;
}

__global__ void zz_kernel(const float* __restrict__ z) {
    int t = blockIdx.x * blockDim.x + threadIdx.x;
    int b = t >> 15, s = t & 32767;
    const float* base = z + ((size_t)b << 23) + s;
    float acc = 0.0f;
#pragma unroll 8
    for (int c = 0; c < EDIM; c++) {
        float v = base[(size_t)c << 15];
        acc = fmaf(v, v, acc);
    }
    g_zz[t] = acc;
}

// ---------------------------------------------------------------------------
// Distance GEMM + argmin. Block tile: 128 tokens x 128 codes (8 nt tiles).
// 256 threads: ty=tid>>4 owns 8 tokens (4 natural ull pairs + swaps),
// tx=tid&15 owns 8 codes as chunks {tx*4..+3} and {64+tx*4..+3} (contiguous
// per 8-lane phase -> conflict-free LDS.128). Per warp-kk: 4 LDS.128 (16
// crossbar cyc) vs 32 FFMA2 (64 fma cyc) -> crossbar no longer binds.
// A staged via 3-buffer cp.async (prefetch distance 2) to cover z DRAM
// latency; B (L2-resident emb) staged distance 1 via regs+STS.
// Numerics bit-identical to R2-R6 (per-(t,n) sequential k, same epilogue).
__global__ void __launch_bounds__(256, 2)
dist_kernel(const float* __restrict__ z, const float* __restrict__ emb,
            float* __restrict__ out) {
    extern __shared__ char smem_raw[];
    // [0    , 24576): As[3][16][128] float  (A: z tile, k-major, 3-stage)
    // [24576, 40960): Bs[2][16][128] float  (B: emb tile, [k][code], 2-stage)
    float (*As)[16][128] = (float(*)[16][128])smem_raw;
    float (*Bs)[16][128] = (float(*)[16][128])(smem_raw + 24576);

    int tid = threadIdx.x;
    int tx = tid & 15;       // code group
    int ty = tid >> 4;       // token group (8 tokens)
    int t0 = blockIdx.x * 128;
    int b = t0 >> 15, s0 = t0 & 32767;
    const float* zb = z + ((size_t)b << 23) + s0;
    // B staging: thread stages 8 floats of one emb row
    int brow  = tid & 127;
    int bhalf = tid >> 7;

    float tzz[8];
#pragma unroll
    for (int i = 0; i < 8; i++) tzz[i] = g_zz[t0 + ty * 8 + i];

    float best[8];
    int   bidx[8];
#pragma unroll
    for (int i = 0; i < 8; i++) { best[i] = 3.4e38f; bidx[i] = 0; }

    for (int nt = 0; nt < 8; nt++) {
        int n0 = nt * 128;
        const float* bsrc = emb + (size_t)(n0 + brow) * EDIM + bhalf * 8;

        ull accA[4][4], accB[4][4];
#pragma unroll
        for (int p = 0; p < 4; p++)
#pragma unroll
            for (int j = 0; j < 4; j++) { accA[p][j] = 0ull; accB[p][j] = 0ull; }

        float bq[8];

        // ---- prologue: A kc=0,1 in flight; B kc=0 staged ----
        {
#pragma unroll
            for (int c = 0; c < 2; c++) {
                int lin = c * 256 + tid;
                int row = lin >> 5, col = (lin & 31) * 4;
                cp_async16(&As[0][row][col], zb + ((size_t)row << 15) + col);
            }
            cp_commit();
            float4 v0 = *(const float4*)(bsrc);
            float4 v1 = *(const float4*)(bsrc + 4);
            bq[0]=v0.x; bq[1]=v0.y; bq[2]=v0.z; bq[3]=v0.w;
            bq[4]=v1.x; bq[5]=v1.y; bq[6]=v1.z; bq[7]=v1.w;
#pragma unroll
            for (int c = 0; c < 2; c++) {
                int lin = c * 256 + tid;
                int row = lin >> 5, col = (lin & 31) * 4;
                cp_async16(&As[1][row][col],
                           zb + ((size_t)(16 + row) << 15) + col);
            }
            cp_commit();
#pragma unroll
            for (int q = 0; q < 8; q++)
                Bs[0][bhalf * 8 + q][brow] = bq[q];
            cp_wait<1>();   // As[0] ready
        }
        __syncthreads();

        for (int kc = 0; kc < 16; kc++) {
            int ab = kc % 3;
            int bb = kc & 1;
            // ---- B global load for kc+1 (L2-resident) ----
            if (kc < 15) {
                const float* p1 = bsrc + (kc + 1) * 16;
                float4 v0 = *(const float4*)(p1);
                float4 v1 = *(const float4*)(p1 + 4);
                bq[0]=v0.x; bq[1]=v0.y; bq[2]=v0.z; bq[3]=v0.w;
                bq[4]=v1.x; bq[5]=v1.y; bq[6]=v1.z; bq[7]=v1.w;
            }
            // ---- A cp.async for kc+2 (distance-2 prefetch) ----
            if (kc < 14) {
                int dst = (kc + 2) % 3;
#pragma unroll
                for (int c = 0; c < 2; c++) {
                    int lin = c * 256 + tid;
                    int row = lin >> 5, col = (lin & 31) * 4;
                    cp_async16(&As[dst][row][col],
                               zb + ((size_t)((kc + 2) * 16 + row) << 15) + col);
                }
                cp_commit();
            }
            // ---- compute kc ----
#pragma unroll
            for (int kk = 0; kk < 16; kk++) {
                ulonglong2 av0 = *(const ulonglong2*)&As[ab][kk][ty * 8];
                ulonglong2 av1 = *(const ulonglong2*)&As[ab][kk][ty * 8 + 4];
                ull a0 = av0.x, a1 = av0.y, a2 = av1.x, a3 = av1.y;
                ull s0v = swap64(a0), s1v = swap64(a1);
                ull s2v = swap64(a2), s3v = swap64(a3);
                ulonglong2 bv0 = *(const ulonglong2*)&Bs[bb][kk][tx * 4];
                ulonglong2 bv1 = *(const ulonglong2*)&Bs[bb][kk][64 + tx * 4];
                ull bp0 = bv0.x, bp1 = bv0.y, bp2 = bv1.x, bp3 = bv1.y;
                accA[0][0] = ffma2(a0, bp0, accA[0][0]);
                accB[0][0] = ffma2(s0v, bp0, accB[0][0]);
                accA[1][0] = ffma2(a1, bp0, accA[1][0]);
                accB[1][0] = ffma2(s1v, bp0, accB[1][0]);
                accA[2][0] = ffma2(a2, bp0, accA[2][0]);
                accB[2][0] = ffma2(s2v, bp0, accB[2][0]);
                accA[3][0] = ffma2(a3, bp0, accA[3][0]);
                accB[3][0] = ffma2(s3v, bp0, accB[3][0]);
                accA[0][1] = ffma2(a0, bp1, accA[0][1]);
                accB[0][1] = ffma2(s0v, bp1, accB[0][1]);
                accA[1][1] = ffma2(a1, bp1, accA[1][1]);
                accB[1][1] = ffma2(s1v, bp1, accB[1][1]);
                accA[2][1] = ffma2(a2, bp1, accA[2][1]);
                accB[2][1] = ffma2(s2v, bp1, accB[2][1]);
                accA[3][1] = ffma2(a3, bp1, accA[3][1]);
                accB[3][1] = ffma2(s3v, bp1, accB[3][1]);
                accA[0][2] = ffma2(a0, bp2, accA[0][2]);
                accB[0][2] = ffma2(s0v, bp2, accB[0][2]);
                accA[1][2] = ffma2(a1, bp2, accA[1][2]);
                accB[1][2] = ffma2(s1v, bp2, accB[1][2]);
                accA[2][2] = ffma2(a2, bp2, accA[2][2]);
                accB[2][2] = ffma2(s2v, bp2, accB[2][2]);
                accA[3][2] = ffma2(a3, bp2, accA[3][2]);
                accB[3][2] = ffma2(s3v, bp2, accB[3][2]);
                accA[0][3] = ffma2(a0, bp3, accA[0][3]);
                accB[0][3] = ffma2(s0v, bp3, accB[0][3]);
                accA[1][3] = ffma2(a1, bp3, accA[1][3]);
                accB[1][3] = ffma2(s1v, bp3, accB[1][3]);
                accA[2][3] = ffma2(a2, bp3, accA[2][3]);
                accB[2][3] = ffma2(s2v, bp3, accB[2][3]);
                accA[3][3] = ffma2(a3, bp3, accA[3][3]);
                accB[3][3] = ffma2(s3v, bp3, accB[3][3]);
            }
            // ---- finish staging ----
            if (kc < 15) {
#pragma unroll
                for (int q = 0; q < 8; q++)
                    Bs[bb ^ 1][bhalf * 8 + q][brow] = bq[q];
            }
            if (kc < 14)      cp_wait<1>();   // As[kc+1] done, As[kc+2] may fly
            else if (kc == 14) cp_wait<0>();  // As[15] done
            __syncthreads();
        }

        // ---- epilogue: d = fl(fl(zz+ee) - 2*dot), lowest-index tiebreak ----
        // accA[tp][bp] = { dot(tokE, nBase), dot(tokO, nBase+1) }
        // accB[tp][bp] = { dot(tokO, nBase), dot(tokE, nBase+1) }
        // nBase = n0 + (bp>>1)*64 + tx*4 + 2*(bp&1); tokE = ty*8+2tp
#pragma unroll
        for (int bp = 0; bp < 4; bp++) {
            int nA = n0 + (bp >> 1) * 64 + tx * 4 + 2 * (bp & 1);
            int nB = nA + 1;
            float eA = g_ee[nA], eB = g_ee[nB];
#pragma unroll
            for (int tp = 0; tp < 4; tp++) {
                int iE = 2 * tp, iO = 2 * tp + 1;
                float2 va = *(float2*)&accA[tp][bp];
                float2 vb = *(float2*)&accB[tp][bp];
                {   // (tokE, nA)
                    float d = __fadd_rn(__fadd_rn(tzz[iE], eA), -2.0f * va.x);
                    if (d < best[iE] || (d == best[iE] && nA < bidx[iE])) {
                        best[iE] = d; bidx[iE] = nA;
                    }
                }
                {   // (tokO, nB)
                    float d = __fadd_rn(__fadd_rn(tzz[iO], eB), -2.0f * va.y);
                    if (d < best[iO] || (d == best[iO] && nB < bidx[iO])) {
                        best[iO] = d; bidx[iO] = nB;
                    }
                }
                {   // (tokO, nA)
                    float d = __fadd_rn(__fadd_rn(tzz[iO], eA), -2.0f * vb.x);
                    if (d < best[iO] || (d == best[iO] && nA < bidx[iO])) {
                        best[iO] = d; bidx[iO] = nA;
                    }
                }
                {   // (tokE, nB)
                    float d = __fadd_rn(__fadd_rn(tzz[iE], eB), -2.0f * vb.y);
                    if (d < best[iE] || (d == best[iE] && nB < bidx[iE])) {
                        best[iE] = d; bidx[iE] = nB;
                    }
                }
            }
        }
    }

    // ---- cross-thread reduction over tx (16 candidates per token) ----
    __syncthreads();
    float* rv = (float*)smem_raw;             // [128][16] = 8KB
    int*   ri = (int*)(smem_raw + 8192);      // [128][16] = 8KB
#pragma unroll
    for (int i = 0; i < 8; i++) {
        rv[(ty * 8 + i) * 16 + tx] = best[i];
        ri[(ty * 8 + i) * 16 + tx] = bidx[i];
    }
    __syncthreads();
    if (tid < 128) {
        float bv = rv[tid * 16 + 0];
        int   bi = ri[tid * 16 + 0];
#pragma unroll
        for (int x = 1; x < 16; x++) {
            float v = rv[tid * 16 + x];
            int   id = ri[tid * 16 + x];
            if (v < bv || (v == bv && id < bi)) { bv = v; bi = id; }
        }
        int t = t0 + tid;
        g_idx[t] = bi;
        out[OFF_IDX + t] = (float)bi;
        out[OFF_SAMP + bi] = 1.0f;   // all writers store 1.0f — benign race
    }
}

// ---------------------------------------------------------------------------
__global__ void zq_kernel(const float* __restrict__ z,
                          const float* __restrict__ emb,
                          float* __restrict__ out) {
    __shared__ int sidx[32];
    __shared__ double red[256];
    int tid = threadIdx.x;
    int t0 = blockIdx.x * 32;
    int b = t0 >> 15, s0 = t0 & 32767;
    if (tid < 32) sidx[tid] = g_idx[t0 + tid];
    __syncthreads();
    size_t zbase = ((size_t)b << 23) + s0;
    double acc = 0.0;
    for (int rep = 0; rep < 32; rep++) {
        int lin = rep * 256 + tid;
        int c = lin >> 5;
        int tok = lin & 31;
        float q = emb[(size_t)sidx[tok] * EDIM + c];
        size_t addr = zbase + ((size_t)c << 15) + tok;
        float zv = z[addr];
        out[OFF_ZQ + addr] = q;
        float d = q - zv;
        acc += (double)d * (double)d;
    }
    red[tid] = acc;
    __syncthreads();
    for (int s = 128; s > 0; s >>= 1) {
        if (tid < s) red[tid] += red[tid + s];
        __syncthreads();
    }
    if (tid == 0) atomicAdd(&g_loss_acc, red[0]);
}

// ---------------------------------------------------------------------------
__global__ void __launch_bounds__(256)
cd_kernel(const float* __restrict__ emb) {
    __shared__ float As[16][128];
    __shared__ float Bs[16][128];
    int tid = threadIdx.x;
    int tx = tid & 15, ty = tid >> 4;
    int i0 = blockIdx.y * 128, j0 = blockIdx.x * 128;

    float acc[8][8];
#pragma unroll
    for (int i = 0; i < 8; i++)
#pragma unroll
        for (int j = 0; j < 8; j++) acc[i][j] = 0.0f;

    for (int kc = 0; kc < 16; kc++) {
        int k0 = kc * 16;
        __syncthreads();
        {
            int n = tid & 127;
            int qb = (tid >> 7) * 2;
#pragma unroll
            for (int w = 0; w < 2; w++) {
                int q = qb + w;
                float4 v = *(const float4*)(emb + (size_t)(i0 + n) * EDIM + k0 + q * 4);
                As[q * 4 + 0][n] = v.x; As[q * 4 + 1][n] = v.y;
                As[q * 4 + 2][n] = v.z; As[q * 4 + 3][n] = v.w;
                float4 u = *(const float4*)(emb + (size_t)(j0 + n) * EDIM + k0 + q * 4);
                Bs[q * 4 + 0][n] = u.x; Bs[q * 4 + 1][n] = u.y;
                Bs[q * 4 + 2][n] = u.z; Bs[q * 4 + 3][n] = u.w;
            }
        }
        __syncthreads();
#pragma unroll
        for (int kk = 0; kk < 16; kk++) {
            float a[8], bb[8];
            float4 a0 = *(float4*)&As[kk][ty * 8];
            float4 a1 = *(float4*)&As[kk][ty * 8 + 4];
            a[0] = a0.x; a[1] = a0.y; a[2] = a0.z; a[3] = a0.w;
            a[4] = a1.x; a[5] = a1.y; a[6] = a1.z; a[7] = a1.w;
            float4 b0 = *(float4*)&Bs[kk][tx * 8];
            float4 b1 = *(float4*)&Bs[kk][tx * 8 + 4];
            bb[0] = b0.x; bb[1] = b0.y; bb[2] = b0.z; bb[3] = b0.w;
            bb[4] = b1.x; bb[5] = b1.y; bb[6] = b1.z; bb[7] = b1.w;
#pragma unroll
            for (int i = 0; i < 8; i++)
#pragma unroll
                for (int j = 0; j < 8; j++)
                    acc[i][j] = fmaf(a[i], bb[j], acc[i][j]);
        }
    }
#pragma unroll
    for (int i = 0; i < 8; i++) {
        int gi = i0 + ty * 8 + i;
        float ei = g_ee[gi];
#pragma unroll
        for (int j = 0; j < 8; j++) {
            int gj = j0 + tx * 8 + j;
            float d = __fadd_rn(__fadd_rn(ei, g_ee[gj]), -2.0f * acc[i][j]);
            g_cd[(size_t)gi * NE + gj] = d;
        }
    }
}

__global__ void cdstats_kernel() {
    __shared__ float  s1[256], s2[256];
    __shared__ double ds[256], dq[256];
    int r = blockIdx.x, tid = threadIdx.x;
    const float* row = g_cd + (size_t)r * NE;
    float a = 3.4e38f, b2 = 3.4e38f;
    double sm = 0.0, sq = 0.0;
    for (int j = tid; j < NE; j += 256) {
        float v = row[j];
        sm += v;
        sq += (double)v * v;
        if (v < a) { b2 = a; a = v; }
        else if (v < b2) { b2 = v; }
    }
    s1[tid] = a; s2[tid] = b2; ds[tid] = sm; dq[tid] = sq;
    __syncthreads();
    for (int s = 128; s > 0; s >>= 1) {
        if (tid < s) {
            float x1 = s1[tid], x2 = s2[tid];
            float y1 = s1[tid + s], y2 = s2[tid + s];
            s1[tid] = fminf(x1, y1);
            s2[tid] = fminf(fmaxf(x1, y1), fminf(x2, y2));
            ds[tid] += ds[tid + s];
            dq[tid] += dq[tid + s];
        }
        __syncthreads();
    }
    if (tid == 0) {
        atomicAdd(&g_min2_acc, (double)s2[0]);
        double S = ds[0], Q = dq[0];
        double var = (Q - S * S / 1024.0) / 1023.0;
        atomicAdd(&g_var_acc, var);
    }
}

__global__ void fin_kernel(float* __restrict__ out) {
    float m = (float)(g_loss_acc / 16777216.0);
    out[OFF_LOSS] = 0.2f * m + m;
    out[OFF_MCD] = (float)(g_min2_acc / 1024.0);
    out[OFF_MCV] = (float)(g_var_acc / 1024.0);
}

// ---------------------------------------------------------------------------
extern "C" void kernel_launch(void* const* d_in, const int* in_sizes, int n_in,
                              void* d_out, int out_size) {
    const float* z   = (const float*)d_in[0];
    const float* emb = (const float*)d_in[1];
    float* out = (float*)d_out;

    cudaFuncSetAttribute(dist_kernel,
                         cudaFuncAttributeMaxDynamicSharedMemorySize, 40960);

    init_kernel<<<8, 256>>>(out);
    ee_kernel<<<4, 256>>>(emb);
    zz_kernel<<<256, 256>>>(z);
    dist_kernel<<<512, 256, 40960>>>(z, emb, out);
    zq_kernel<<<2048, 256>>>(z, emb, out);
    cd_kernel<<<dim3(8, 8), 256>>>(emb);
    cdstats_kernel<<<1024, 256>>>();
    fin_kernel<<<1, 1>>>(out);
}